// round 1
// baseline (speedup 1.0000x reference)
#include <cuda_runtime.h>
#include <math.h>
#include <float.h>

// ---------------- problem constants ----------------
#define NN      50000      // nodes
#define NE      600000     // edges
#define DD      128        // feature dim
#define NET     4          // edge types
#define NSTEPS  5
#define NHEADS  2
#define NG      64         // graphs
#define NCLS    32

// ---------------- device scratch (static, allocation-free) ----------------
__device__ float g_h  [NN * DD];           // current node state
__device__ float g_t  [(size_t)NN * NET * DD]; // per-etype transform, layout [n][etype*128+o]
__device__ float g_a  [NN * DD];           // aggregated messages
__device__ float g_gi [NN * 3 * DD];       // GRU input gates
__device__ float g_gh [NN * 3 * DD];       // GRU hidden gates
__device__ float g_zft[NN * NHEADS * DD];  // GAT features [n][hd*128+d]
__device__ float g_el [NN * NHEADS];
__device__ float g_er [NN * NHEADS];
__device__ float g_ge [NE * NHEADS];       // edge logits -> alpha
__device__ float g_rst[NN * NHEADS * DD];  // GAT output (post bias+relu)
__device__ float g_logits[2][NG * NHEADS * NCLS];

__device__ int g_deg   [NN];
__device__ int g_indptr[NN + 1];
__device__ int g_cursor[NN];
__device__ int g_eids  [NE];
__device__ int g_gs    [NG + 1];

__device__ __forceinline__ float sigf(float x) { return 1.f / (1.f + expf(-x)); }

// ---------------- misc small kernels ----------------
__global__ void copy_h(const float* __restrict__ f) {
    int i = blockIdx.x * blockDim.x + threadIdx.x;
    if (i < NN * (DD / 4)) ((float4*)g_h)[i] = ((const float4*)f)[i];
}

__global__ void zero_deg() {
    int i = blockIdx.x * blockDim.x + threadIdx.x;
    if (i < NN) g_deg[i] = 0;
}

__global__ void count_deg(const int* __restrict__ dst) {
    int e = blockIdx.x * blockDim.x + threadIdx.x;
    if (e < NE) atomicAdd(&g_deg[dst[e]], 1);
}

// single-block exclusive scan over g_deg -> g_indptr, g_cursor
__global__ void scan_deg() {
    __shared__ int wsum[32];
    __shared__ int carry;
    int tid = threadIdx.x;  // 1024 threads
    if (tid == 0) carry = 0;
    __syncthreads();
    for (int base = 0; base < NN; base += 1024) {
        int i = base + tid;
        int v = (i < NN) ? g_deg[i] : 0;
        int x = v;
        #pragma unroll
        for (int o = 1; o < 32; o <<= 1) {
            int y = __shfl_up_sync(0xffffffffu, x, o);
            if ((tid & 31) >= o) x += y;
        }
        if ((tid & 31) == 31) wsum[tid >> 5] = x;
        __syncthreads();
        if (tid < 32) {
            int wv = wsum[tid];
            int xs = wv;
            #pragma unroll
            for (int o = 1; o < 32; o <<= 1) {
                int y = __shfl_up_sync(0xffffffffu, xs, o);
                if (tid >= o) xs += y;
            }
            wsum[tid] = xs - wv;  // exclusive
        }
        __syncthreads();
        int excl = (x - v) + wsum[tid >> 5] + carry;
        if (i < NN) { g_indptr[i] = excl; g_cursor[i] = excl; }
        __syncthreads();
        if (tid == 1023) carry = excl + v;
        __syncthreads();
    }
    if (tid == 0) g_indptr[NN] = carry;
}

__global__ void build_eids(const int* __restrict__ dst) {
    int e = blockIdx.x * blockDim.x + threadIdx.x;
    if (e < NE) {
        int p = atomicAdd(&g_cursor[dst[e]], 1);
        g_eids[p] = e;
    }
}

// ---------------- FP32 tiled GEMM: C[n,o] = sum_d A[n,d]*B[o,d] + bias[o] ----------------
// A selected by aSel (0: g_h, 1: g_a); C by cSel (0: g_t, 1: g_gh, 2: g_gi, 3: g_zft)
__global__ __launch_bounds__(256, 2)
void gemm_bias(int aSel, const float* __restrict__ B, const float* __restrict__ bias,
               int cSel, int outDim) {
    __shared__ float As[32][128];
    __shared__ float Bs[32][128];

    const float* A = aSel ? g_a : g_h;
    float* C;
    switch (cSel) {
        case 0: C = g_t;  break;
        case 1: C = g_gh; break;
        case 2: C = g_gi; break;
        default: C = g_zft; break;
    }
    const int n = NN;
    const int tid = threadIdx.x;
    const int rowBase = blockIdx.x * 128;
    const int colBase = blockIdx.y * 128;
    const int ty = tid >> 4, tx = tid & 15;

    float acc[8][8];
    #pragma unroll
    for (int i = 0; i < 8; i++)
        #pragma unroll
        for (int j = 0; j < 8; j++) acc[i][j] = 0.f;

    const int lr = tid >> 1;         // 0..127 (tile row)
    const int lh = (tid & 1) * 16;   // k half offset

    for (int kc = 0; kc < 128; kc += 32) {
        int ga = rowBase + lr;
        const float4* Ap = (ga < n) ? (const float4*)(A + (size_t)ga * 128 + kc + lh) : nullptr;
        const float4* Bp = (const float4*)(B + (size_t)(colBase + lr) * 128 + kc + lh);
        #pragma unroll
        for (int i = 0; i < 4; i++) {
            float4 av = Ap ? Ap[i] : make_float4(0.f, 0.f, 0.f, 0.f);
            float4 bv = Bp[i];
            int k0 = lh + i * 4;
            As[k0 + 0][lr] = av.x; As[k0 + 1][lr] = av.y;
            As[k0 + 2][lr] = av.z; As[k0 + 3][lr] = av.w;
            Bs[k0 + 0][lr] = bv.x; Bs[k0 + 1][lr] = bv.y;
            Bs[k0 + 2][lr] = bv.z; Bs[k0 + 3][lr] = bv.w;
        }
        __syncthreads();
        #pragma unroll
        for (int kk = 0; kk < 32; kk++) {
            float4 a0 = *(const float4*)&As[kk][ty * 8];
            float4 a1 = *(const float4*)&As[kk][ty * 8 + 4];
            float4 b0 = *(const float4*)&Bs[kk][tx * 8];
            float4 b1 = *(const float4*)&Bs[kk][tx * 8 + 4];
            float ar[8] = {a0.x, a0.y, a0.z, a0.w, a1.x, a1.y, a1.z, a1.w};
            float br[8] = {b0.x, b0.y, b0.z, b0.w, b1.x, b1.y, b1.z, b1.w};
            #pragma unroll
            for (int i = 0; i < 8; i++)
                #pragma unroll
                for (int j = 0; j < 8; j++) acc[i][j] += ar[i] * br[j];
        }
        __syncthreads();
    }

    #pragma unroll
    for (int i = 0; i < 8; i++) {
        int row = rowBase + ty * 8 + i;
        if (row >= n) continue;
        float* Cp = C + (size_t)row * outDim + colBase + tx * 8;
        #pragma unroll
        for (int j = 0; j < 8; j++) {
            float b = bias ? bias[colBase + tx * 8 + j] : 0.f;
            Cp[j] = acc[i][j] + b;
        }
    }
}

// ---------------- message aggregation: a[n] = sum over in-edges of t[src][etype] ----------------
__global__ void aggregate(const int* __restrict__ src, const int* __restrict__ et) {
    int w = (blockIdx.x * blockDim.x + threadIdx.x) >> 5;
    if (w >= NN) return;
    int lane = threadIdx.x & 31;
    int s0 = g_indptr[w], s1 = g_indptr[w + 1];
    float4 acc = make_float4(0.f, 0.f, 0.f, 0.f);
    for (int p = s0; p < s1; p++) {
        int e = g_eids[p];
        int s = src[e];
        int k = et[e];
        float4 v = ((const float4*)(g_t + (size_t)s * (NET * DD) + k * DD))[lane];
        acc.x += v.x; acc.y += v.y; acc.z += v.z; acc.w += v.w;
    }
    ((float4*)(g_a + (size_t)w * DD))[lane] = acc;
}

// ---------------- GRU elementwise update ----------------
__global__ void gru_update() {
    int idx = blockIdx.x * blockDim.x + threadIdx.x;
    if (idx >= NN * 32) return;
    int n = idx >> 5, q = idx & 31;
    const float4* gi = (const float4*)(g_gi + (size_t)n * 384);
    const float4* gh = (const float4*)(g_gh + (size_t)n * 384);
    float4* hp = (float4*)(g_h + (size_t)n * 128);
    float4 ir = gi[q], iz = gi[q + 32], inn = gi[q + 64];
    float4 hr = gh[q], hz = gh[q + 32], hn = gh[q + 64];
    float4 h = hp[q];
    float4 o;
    {
        float r = sigf(ir.x + hr.x), z = sigf(iz.x + hz.x);
        float nn2 = tanhf(inn.x + r * hn.x);
        o.x = (1.f - z) * nn2 + z * h.x;
    }
    {
        float r = sigf(ir.y + hr.y), z = sigf(iz.y + hz.y);
        float nn2 = tanhf(inn.y + r * hn.y);
        o.y = (1.f - z) * nn2 + z * h.y;
    }
    {
        float r = sigf(ir.z + hr.z), z = sigf(iz.z + hz.z);
        float nn2 = tanhf(inn.z + r * hn.z);
        o.z = (1.f - z) * nn2 + z * h.z;
    }
    {
        float r = sigf(ir.w + hr.w), z = sigf(iz.w + hz.w);
        float nn2 = tanhf(inn.w + r * hn.w);
        o.w = (1.f - z) * nn2 + z * h.w;
    }
    hp[q] = o;
}

// ---------------- row L2-normalize + sigmoid ----------------
__global__ void norm_sigmoid() {
    int w = (blockIdx.x * blockDim.x + threadIdx.x) >> 5;
    if (w >= NN) return;
    int lane = threadIdx.x & 31;
    float4* p = (float4*)(g_h + (size_t)w * 128);
    float4 v = p[lane];
    float ss = v.x * v.x + v.y * v.y + v.z * v.z + v.w * v.w;
    #pragma unroll
    for (int o = 16; o; o >>= 1) ss += __shfl_xor_sync(0xffffffffu, ss, o);
    float inv = 1.f / fmaxf(sqrtf(ss), 1e-12f);
    v.x = sigf(v.x * inv); v.y = sigf(v.y * inv);
    v.z = sigf(v.z * inv); v.w = sigf(v.w * inv);
    p[lane] = v;
}

// ---------------- GAT attention scalars el/er per node ----------------
__global__ void elr_kernel(const float* __restrict__ al, const float* __restrict__ ar) {
    int w = (blockIdx.x * blockDim.x + threadIdx.x) >> 5;
    if (w >= NN) return;
    int lane = threadIdx.x & 31;
    const float4* z = (const float4*)(g_zft + (size_t)w * 256);
    const float4* al4 = (const float4*)al;
    const float4* ar4 = (const float4*)ar;
    #pragma unroll
    for (int hd = 0; hd < 2; hd++) {
        float4 zv = z[hd * 32 + lane];
        float4 lv = al4[hd * 32 + lane];
        float4 rv = ar4[hd * 32 + lane];
        float pl = zv.x * lv.x + zv.y * lv.y + zv.z * lv.z + zv.w * lv.w;
        float pr = zv.x * rv.x + zv.y * rv.y + zv.z * rv.z + zv.w * rv.w;
        #pragma unroll
        for (int o = 16; o; o >>= 1) {
            pl += __shfl_xor_sync(0xffffffffu, pl, o);
            pr += __shfl_xor_sync(0xffffffffu, pr, o);
        }
        if (lane == 0) { g_el[w * 2 + hd] = pl; g_er[w * 2 + hd] = pr; }
    }
}

// ---------------- GAT edge logits ----------------
__global__ void edge_e(const int* __restrict__ src, const int* __restrict__ dst) {
    int e = blockIdx.x * blockDim.x + threadIdx.x;
    if (e >= NE) return;
    int s = src[e], d = dst[e];
    #pragma unroll
    for (int hd = 0; hd < 2; hd++) {
        float x = g_el[s * 2 + hd] + g_er[d * 2 + hd];
        g_ge[e * 2 + hd] = x > 0.f ? x : 0.2f * x;
    }
}

// ---------------- per-dst edge softmax (writes alpha into g_ge) ----------------
__global__ void node_softmax() {
    int w = (blockIdx.x * blockDim.x + threadIdx.x) >> 5;
    if (w >= NN) return;
    int lane = threadIdx.x & 31;
    int s0 = g_indptr[w], s1 = g_indptr[w + 1];
    if (s0 == s1) return;
    float m0 = -FLT_MAX, m1 = -FLT_MAX;
    for (int p = s0 + lane; p < s1; p += 32) {
        int e = g_eids[p];
        m0 = fmaxf(m0, g_ge[e * 2]);
        m1 = fmaxf(m1, g_ge[e * 2 + 1]);
    }
    #pragma unroll
    for (int o = 16; o; o >>= 1) {
        m0 = fmaxf(m0, __shfl_xor_sync(0xffffffffu, m0, o));
        m1 = fmaxf(m1, __shfl_xor_sync(0xffffffffu, m1, o));
    }
    float d0 = 0.f, d1 = 0.f;
    for (int p = s0 + lane; p < s1; p += 32) {
        int e = g_eids[p];
        d0 += expf(g_ge[e * 2] - m0);
        d1 += expf(g_ge[e * 2 + 1] - m1);
    }
    #pragma unroll
    for (int o = 16; o; o >>= 1) {
        d0 += __shfl_xor_sync(0xffffffffu, d0, o);
        d1 += __shfl_xor_sync(0xffffffffu, d1, o);
    }
    float i0 = 1.f / d0, i1 = 1.f / d1;
    for (int p = s0 + lane; p < s1; p += 32) {
        int e = g_eids[p];
        g_ge[e * 2]     = expf(g_ge[e * 2] - m0) * i0;
        g_ge[e * 2 + 1] = expf(g_ge[e * 2 + 1] - m1) * i1;
    }
}

// ---------------- GAT accumulation + bias + relu ----------------
__global__ void gat_accum(const int* __restrict__ src, const float* __restrict__ gbias) {
    int w = (blockIdx.x * blockDim.x + threadIdx.x) >> 5;
    if (w >= NN) return;
    int lane = threadIdx.x & 31;
    int s0 = g_indptr[w], s1 = g_indptr[w + 1];
    float4 a0 = make_float4(0.f, 0.f, 0.f, 0.f);
    float4 a1 = make_float4(0.f, 0.f, 0.f, 0.f);
    for (int p = s0; p < s1; p++) {
        int e = g_eids[p];
        int s = src[e];
        float al0 = g_ge[e * 2], al1 = g_ge[e * 2 + 1];
        const float4* z = (const float4*)(g_zft + (size_t)s * 256);
        float4 z0 = z[lane], z1 = z[32 + lane];
        a0.x += al0 * z0.x; a0.y += al0 * z0.y; a0.z += al0 * z0.z; a0.w += al0 * z0.w;
        a1.x += al1 * z1.x; a1.y += al1 * z1.y; a1.z += al1 * z1.z; a1.w += al1 * z1.w;
    }
    const float4* b4 = (const float4*)gbias;
    float4 b0 = b4[lane], b1 = b4[32 + lane];
    float4 o0, o1;
    o0.x = fmaxf(a0.x + b0.x, 0.f); o0.y = fmaxf(a0.y + b0.y, 0.f);
    o0.z = fmaxf(a0.z + b0.z, 0.f); o0.w = fmaxf(a0.w + b0.w, 0.f);
    o1.x = fmaxf(a1.x + b1.x, 0.f); o1.y = fmaxf(a1.y + b1.y, 0.f);
    o1.z = fmaxf(a1.z + b1.z, 0.f); o1.w = fmaxf(a1.w + b1.w, 0.f);
    float4* outp = (float4*)(g_rst + (size_t)w * 256);
    outp[lane] = o0;
    outp[32 + lane] = o1;
}

// ---------------- graph boundaries via binary search on sorted gid ----------------
__global__ void graph_bounds(const int* __restrict__ gid) {
    int b = threadIdx.x;
    if (b > NG) return;
    if (b == NG) { g_gs[NG] = NN; return; }
    int lo = 0, hi = NN;
    while (lo < hi) {
        int mid = (lo + hi) >> 1;
        if (gid[mid] < b) lo = mid + 1; else hi = mid;
    }
    g_gs[b] = lo;
}

// ---------------- mean pool per graph + classify ----------------
__global__ void pool_classify(const float* __restrict__ Wc, const float* __restrict__ bc, int gidx) {
    __shared__ float sh[256];
    int b = blockIdx.x;
    int t = threadIdx.x;  // 256
    int s = g_gs[b], e2 = g_gs[b + 1];
    float sum = 0.f;
    for (int r = s; r < e2; r++) sum += g_rst[(size_t)r * 256 + t];
    sh[t] = sum / fmaxf((float)(e2 - s), 1.f);
    __syncthreads();
    if (t < 64) {
        int hd = t >> 5, c = t & 31;
        float acc = bc[c];
        const float* hp = sh + hd * 128;
        const float* wp = Wc + c * 128;
        #pragma unroll 8
        for (int d2 = 0; d2 < 128; d2++) acc += hp[d2] * wp[d2];
        g_logits[gidx][(b * 2 + hd) * 32 + c] = acc;
    }
}

// ---------------- final distance + head softmax ----------------
__global__ void final_kernel(float* __restrict__ out) {
    int b = threadIdx.x;
    if (b >= NG) return;
    float dv[2];
    #pragma unroll
    for (int hd = 0; hd < 2; hd++) {
        float ss = 0.f;
        #pragma unroll
        for (int c = 0; c < 32; c++) {
            float df = g_logits[0][(b * 2 + hd) * 32 + c]
                     - g_logits[1][(b * 2 + hd) * 32 + c] + 1e-6f;
            ss += df * df;
        }
        dv[hd] = sqrtf(ss);
    }
    float mx = fmaxf(dv[0], dv[1]);
    float e0 = expf(dv[0] - mx), e1 = expf(dv[1] - mx);
    float inv = 1.f / (e0 + e1);
    out[b * 2] = e0 * inv;
    out[b * 2 + 1] = e1 * inv;
}

// ---------------- host driver ----------------
extern "C" void kernel_launch(void* const* d_in, const int* in_sizes, int n_in,
                              void* d_out, int out_size) {
    const float* in1  = (const float*)d_in[0];
    const float* in2  = (const float*)d_in[1];
    const int* src1 = (const int*)d_in[2];
    const int* dst1 = (const int*)d_in[3];
    const int* et1  = (const int*)d_in[4];
    const int* gid1 = (const int*)d_in[5];
    const int* src2 = (const int*)d_in[6];
    const int* dst2 = (const int*)d_in[7];
    const int* et2  = (const int*)d_in[8];
    const int* gid2 = (const int*)d_in[9];
    const float* W_et  = (const float*)d_in[10];
    const float* b_et  = (const float*)d_in[11];
    const float* W_ih  = (const float*)d_in[12];
    const float* W_hh  = (const float*)d_in[13];
    const float* b_ih  = (const float*)d_in[14];
    const float* b_hh  = (const float*)d_in[15];
    const float* W_fc  = (const float*)d_in[16];
    const float* al    = (const float*)d_in[17];
    const float* ar    = (const float*)d_in[18];
    const float* gb    = (const float*)d_in[19];
    const float* W_cls = (const float*)d_in[20];
    const float* b_cls = (const float*)d_in[21];

    const int NBLK_E = (NE + 255) / 256;
    const int NBLK_N = (NN + 255) / 256;
    const int NBLK_W = NN / 8;              // warp-per-node, 8 warps/block (50000/8 = 6250)
    const dim3 gT(391, 4), g3(391, 3), g2d(391, 2);

    for (int g = 0; g < 2; g++) {
        const float* feat = g ? in2 : in1;
        const int* src = g ? src2 : src1;
        const int* dst = g ? dst2 : dst1;
        const int* et  = g ? et2 : et1;
        const int* gid = g ? gid2 : gid1;

        copy_h<<<(NN * 32 + 255) / 256, 256>>>(feat);
        zero_deg<<<NBLK_N, 256>>>();
        count_deg<<<NBLK_E, 256>>>(dst);
        scan_deg<<<1, 1024>>>();
        build_eids<<<NBLK_E, 256>>>(dst);

        for (int s = 0; s < NSTEPS; s++) {
            gemm_bias<<<gT, 256>>>(0, W_et, b_et, 0, 512);   // t = h @ W_et^T + b_et
            gemm_bias<<<g3, 256>>>(0, W_hh, b_hh, 1, 384);   // gh = h @ W_hh^T + b_hh
            aggregate<<<NBLK_W, 256>>>(src, et);             // a = segment_sum msg
            gemm_bias<<<g3, 256>>>(1, W_ih, b_ih, 2, 384);   // gi = a @ W_ih^T + b_ih
            gru_update<<<(NN * 32 + 255) / 256, 256>>>();
        }
        norm_sigmoid<<<NBLK_W, 256>>>();
        gemm_bias<<<g2d, 256>>>(0, W_fc, nullptr, 3, 256);   // zft
        elr_kernel<<<NBLK_W, 256>>>(al, ar);
        edge_e<<<NBLK_E, 256>>>(src, dst);
        node_softmax<<<NBLK_W, 256>>>();
        gat_accum<<<NBLK_W, 256>>>(src, gb);
        graph_bounds<<<1, NG + 1>>>(gid);
        pool_classify<<<NG, 256>>>(W_cls, b_cls, g);
    }
    final_kernel<<<1, NG>>>((float*)d_out);
}

// round 2
// speedup vs baseline: 3.0982x; 3.0982x over previous
#include <cuda_runtime.h>
#include <math.h>
#include <float.h>

// ---------------- problem constants ----------------
#define NN      50000      // nodes
#define NE      600000     // edges
#define DD      128        // feature dim
#define NET     4          // edge types
#define NSTEPS  5
#define NHEADS  2
#define NG      64         // graphs
#define NCLS    32

// ---------------- device scratch (static, allocation-free) ----------------
__device__ float g_h  [NN * DD];           // current node state
__device__ float g_t  [(size_t)NN * NET * DD]; // per-etype transform, layout [n][etype*128+o]
__device__ float g_a  [NN * DD];           // aggregated messages
__device__ float g_gi [NN * 3 * DD];       // GRU input gates
__device__ float g_gh [NN * 3 * DD];       // GRU hidden gates
__device__ float g_zft[NN * NHEADS * DD];  // GAT features [n][hd*128+d]
__device__ float g_el [NN * NHEADS];
__device__ float g_er [NN * NHEADS];
__device__ float g_ge [NE * NHEADS];       // edge logits -> alpha
__device__ float g_rst[NN * NHEADS * DD];  // GAT output (post bias+relu)
__device__ float g_logits[2][NG * NHEADS * NCLS];

__device__ int g_deg   [NN];
__device__ int g_indptr[NN + 1];
__device__ int g_cursor[NN];
__device__ int g_eids  [NE];
__device__ int g_gs    [NG + 1];

__device__ __forceinline__ float sigf(float x) { return 1.f / (1.f + expf(-x)); }

__device__ __forceinline__ unsigned f2tf32(float x) {
    unsigned r;
    asm("cvt.rna.tf32.f32 %0, %1;" : "=r"(r) : "f"(x));
    return r;
}

// ---------------- misc small kernels ----------------
__global__ void copy_h(const float* __restrict__ f) {
    int i = blockIdx.x * blockDim.x + threadIdx.x;
    if (i < NN * (DD / 4)) ((float4*)g_h)[i] = ((const float4*)f)[i];
}

__global__ void zero_deg() {
    int i = blockIdx.x * blockDim.x + threadIdx.x;
    if (i < NN) g_deg[i] = 0;
}

__global__ void count_deg(const int* __restrict__ dst) {
    int e = blockIdx.x * blockDim.x + threadIdx.x;
    if (e < NE) atomicAdd(&g_deg[dst[e]], 1);
}

// single-block exclusive scan over g_deg -> g_indptr, g_cursor
__global__ void scan_deg() {
    __shared__ int wsum[32];
    __shared__ int carry;
    int tid = threadIdx.x;  // 1024 threads
    if (tid == 0) carry = 0;
    __syncthreads();
    for (int base = 0; base < NN; base += 1024) {
        int i = base + tid;
        int v = (i < NN) ? g_deg[i] : 0;
        int x = v;
        #pragma unroll
        for (int o = 1; o < 32; o <<= 1) {
            int y = __shfl_up_sync(0xffffffffu, x, o);
            if ((tid & 31) >= o) x += y;
        }
        if ((tid & 31) == 31) wsum[tid >> 5] = x;
        __syncthreads();
        if (tid < 32) {
            int wv = wsum[tid];
            int xs = wv;
            #pragma unroll
            for (int o = 1; o < 32; o <<= 1) {
                int y = __shfl_up_sync(0xffffffffu, xs, o);
                if (tid >= o) xs += y;
            }
            wsum[tid] = xs - wv;  // exclusive
        }
        __syncthreads();
        int excl = (x - v) + wsum[tid >> 5] + carry;
        if (i < NN) { g_indptr[i] = excl; g_cursor[i] = excl; }
        __syncthreads();
        if (tid == 1023) carry = excl + v;
        __syncthreads();
    }
    if (tid == 0) g_indptr[NN] = carry;
}

__global__ void build_eids(const int* __restrict__ dst) {
    int e = blockIdx.x * blockDim.x + threadIdx.x;
    if (e < NE) {
        int p = atomicAdd(&g_cursor[dst[e]], 1);
        g_eids[p] = e;
    }
}

// ---------------- TF32 tensor-core GEMM: C[n,o] = sum_d A[n,d]*W[o,d] + bias[o] ----------------
// A selected by aSel (0: g_h, 1: g_a); C by cSel (0: g_t, 1: g_gh, 2: g_gi, 3: g_zft)
// Block tile 128x128, K=128 in chunks of 32. 8 warps, each 64x32 via m16n8k8 tf32 mma.
#define SPAD 36   // smem row stride (32 k + 4 pad) in words
__global__ __launch_bounds__(256, 2)
void gemm_tf32(int aSel, const float* __restrict__ B, const float* __restrict__ bias,
               int cSel, int outDim) {
    __shared__ unsigned As[128 * SPAD];
    __shared__ unsigned Bs[128 * SPAD];

    const float* A = aSel ? g_a : g_h;
    float* C;
    switch (cSel) {
        case 0: C = g_t;  break;
        case 1: C = g_gh; break;
        case 2: C = g_gi; break;
        default: C = g_zft; break;
    }
    const int tid = threadIdx.x;
    const int lane = tid & 31;
    const int wid = tid >> 5;
    const int wm = wid >> 2;          // 0..1 -> row block of 64
    const int wn = wid & 3;           // 0..3 -> col block of 32
    const int g8 = lane >> 2;         // group id 0..7
    const int t4 = lane & 3;          // thread-in-group 0..3
    const int rowBase = blockIdx.x * 128;
    const int colBase = blockIdx.y * 128;

    float c[4][4][4];
    #pragma unroll
    for (int mt = 0; mt < 4; mt++)
        #pragma unroll
        for (int nt = 0; nt < 4; nt++)
            #pragma unroll
            for (int i = 0; i < 4; i++) c[mt][nt][i] = 0.f;

    const int lr = tid >> 1;          // 0..127
    const int lh = (tid & 1) * 16;    // k half offset

    for (int kc = 0; kc < 128; kc += 32) {
        // stage A and B chunk into smem, converting to tf32 bits
        {
            int ga = rowBase + lr;
            const float4* Ap = (const float4*)(A + (size_t)ga * 128 + kc + lh);
            const float4* Bp = (const float4*)(B + (size_t)(colBase + lr) * 128 + kc + lh);
            #pragma unroll
            for (int i = 0; i < 4; i++) {
                float4 av = (ga < NN) ? Ap[i] : make_float4(0.f, 0.f, 0.f, 0.f);
                float4 bv = Bp[i];
                uint4 at, bt;
                at.x = f2tf32(av.x); at.y = f2tf32(av.y);
                at.z = f2tf32(av.z); at.w = f2tf32(av.w);
                bt.x = f2tf32(bv.x); bt.y = f2tf32(bv.y);
                bt.z = f2tf32(bv.z); bt.w = f2tf32(bv.w);
                *(uint4*)&As[lr * SPAD + lh + i * 4] = at;
                *(uint4*)&Bs[lr * SPAD + lh + i * 4] = bt;
            }
        }
        __syncthreads();

        #pragma unroll
        for (int k8 = 0; k8 < 4; k8++) {
            const int kb = k8 * 8;
            unsigned af[4][4];   // [mt][reg]
            unsigned bf[4][2];   // [nt][reg]
            #pragma unroll
            for (int mt = 0; mt < 4; mt++) {
                int r0 = wm * 64 + mt * 16 + g8;
                af[mt][0] = As[r0 * SPAD + kb + t4];
                af[mt][1] = As[(r0 + 8) * SPAD + kb + t4];
                af[mt][2] = As[r0 * SPAD + kb + t4 + 4];
                af[mt][3] = As[(r0 + 8) * SPAD + kb + t4 + 4];
            }
            #pragma unroll
            for (int nt = 0; nt < 4; nt++) {
                int n0 = wn * 32 + nt * 8 + g8;
                bf[nt][0] = Bs[n0 * SPAD + kb + t4];
                bf[nt][1] = Bs[n0 * SPAD + kb + t4 + 4];
            }
            #pragma unroll
            for (int mt = 0; mt < 4; mt++)
                #pragma unroll
                for (int nt = 0; nt < 4; nt++) {
                    asm volatile(
                        "mma.sync.aligned.m16n8k8.row.col.f32.tf32.tf32.f32 "
                        "{%0,%1,%2,%3}, {%4,%5,%6,%7}, {%8,%9}, {%0,%1,%2,%3};\n"
                        : "+f"(c[mt][nt][0]), "+f"(c[mt][nt][1]),
                          "+f"(c[mt][nt][2]), "+f"(c[mt][nt][3])
                        : "r"(af[mt][0]), "r"(af[mt][1]), "r"(af[mt][2]), "r"(af[mt][3]),
                          "r"(bf[nt][0]), "r"(bf[nt][1]));
                }
        }
        __syncthreads();
    }

    // epilogue: bias + store
    #pragma unroll
    for (int mt = 0; mt < 4; mt++) {
        int r0 = rowBase + wm * 64 + mt * 16 + g8;
        #pragma unroll
        for (int nt = 0; nt < 4; nt++) {
            int col = colBase + wn * 32 + nt * 8 + 2 * t4;
            float b0 = bias ? bias[col] : 0.f;
            float b1 = bias ? bias[col + 1] : 0.f;
            if (r0 < NN) {
                float2 v0 = make_float2(c[mt][nt][0] + b0, c[mt][nt][1] + b1);
                *(float2*)(C + (size_t)r0 * outDim + col) = v0;
            }
            if (r0 + 8 < NN) {
                float2 v1 = make_float2(c[mt][nt][2] + b0, c[mt][nt][3] + b1);
                *(float2*)(C + (size_t)(r0 + 8) * outDim + col) = v1;
            }
        }
    }
}

// ---------------- message aggregation: a[n] = sum over in-edges of t[src][etype] ----------------
__global__ void aggregate(const int* __restrict__ src, const int* __restrict__ et) {
    int w = (blockIdx.x * blockDim.x + threadIdx.x) >> 5;
    if (w >= NN) return;
    int lane = threadIdx.x & 31;
    int s0 = g_indptr[w], s1 = g_indptr[w + 1];
    float4 acc = make_float4(0.f, 0.f, 0.f, 0.f);
    for (int p = s0; p < s1; p++) {
        int e = g_eids[p];
        int s = src[e];
        int k = et[e];
        float4 v = ((const float4*)(g_t + (size_t)s * (NET * DD) + k * DD))[lane];
        acc.x += v.x; acc.y += v.y; acc.z += v.z; acc.w += v.w;
    }
    ((float4*)(g_a + (size_t)w * DD))[lane] = acc;
}

// ---------------- GRU elementwise update ----------------
__global__ void gru_update() {
    int idx = blockIdx.x * blockDim.x + threadIdx.x;
    if (idx >= NN * 32) return;
    int n = idx >> 5, q = idx & 31;
    const float4* gi = (const float4*)(g_gi + (size_t)n * 384);
    const float4* gh = (const float4*)(g_gh + (size_t)n * 384);
    float4* hp = (float4*)(g_h + (size_t)n * 128);
    float4 ir = gi[q], iz = gi[q + 32], inn = gi[q + 64];
    float4 hr = gh[q], hz = gh[q + 32], hn = gh[q + 64];
    float4 h = hp[q];
    float4 o;
    {
        float r = sigf(ir.x + hr.x), z = sigf(iz.x + hz.x);
        float nn2 = tanhf(inn.x + r * hn.x);
        o.x = (1.f - z) * nn2 + z * h.x;
    }
    {
        float r = sigf(ir.y + hr.y), z = sigf(iz.y + hz.y);
        float nn2 = tanhf(inn.y + r * hn.y);
        o.y = (1.f - z) * nn2 + z * h.y;
    }
    {
        float r = sigf(ir.z + hr.z), z = sigf(iz.z + hz.z);
        float nn2 = tanhf(inn.z + r * hn.z);
        o.z = (1.f - z) * nn2 + z * h.z;
    }
    {
        float r = sigf(ir.w + hr.w), z = sigf(iz.w + hz.w);
        float nn2 = tanhf(inn.w + r * hn.w);
        o.w = (1.f - z) * nn2 + z * h.w;
    }
    hp[q] = o;
}

// ---------------- row L2-normalize + sigmoid ----------------
__global__ void norm_sigmoid() {
    int w = (blockIdx.x * blockDim.x + threadIdx.x) >> 5;
    if (w >= NN) return;
    int lane = threadIdx.x & 31;
    float4* p = (float4*)(g_h + (size_t)w * 128);
    float4 v = p[lane];
    float ss = v.x * v.x + v.y * v.y + v.z * v.z + v.w * v.w;
    #pragma unroll
    for (int o = 16; o; o >>= 1) ss += __shfl_xor_sync(0xffffffffu, ss, o);
    float inv = 1.f / fmaxf(sqrtf(ss), 1e-12f);
    v.x = sigf(v.x * inv); v.y = sigf(v.y * inv);
    v.z = sigf(v.z * inv); v.w = sigf(v.w * inv);
    p[lane] = v;
}

// ---------------- GAT attention scalars el/er per node ----------------
__global__ void elr_kernel(const float* __restrict__ al, const float* __restrict__ ar) {
    int w = (blockIdx.x * blockDim.x + threadIdx.x) >> 5;
    if (w >= NN) return;
    int lane = threadIdx.x & 31;
    const float4* z = (const float4*)(g_zft + (size_t)w * 256);
    const float4* al4 = (const float4*)al;
    const float4* ar4 = (const float4*)ar;
    #pragma unroll
    for (int hd = 0; hd < 2; hd++) {
        float4 zv = z[hd * 32 + lane];
        float4 lv = al4[hd * 32 + lane];
        float4 rv = ar4[hd * 32 + lane];
        float pl = zv.x * lv.x + zv.y * lv.y + zv.z * lv.z + zv.w * lv.w;
        float pr = zv.x * rv.x + zv.y * rv.y + zv.z * rv.z + zv.w * rv.w;
        #pragma unroll
        for (int o = 16; o; o >>= 1) {
            pl += __shfl_xor_sync(0xffffffffu, pl, o);
            pr += __shfl_xor_sync(0xffffffffu, pr, o);
        }
        if (lane == 0) { g_el[w * 2 + hd] = pl; g_er[w * 2 + hd] = pr; }
    }
}

// ---------------- GAT edge logits ----------------
__global__ void edge_e(const int* __restrict__ src, const int* __restrict__ dst) {
    int e = blockIdx.x * blockDim.x + threadIdx.x;
    if (e >= NE) return;
    int s = src[e], d = dst[e];
    #pragma unroll
    for (int hd = 0; hd < 2; hd++) {
        float x = g_el[s * 2 + hd] + g_er[d * 2 + hd];
        g_ge[e * 2 + hd] = x > 0.f ? x : 0.2f * x;
    }
}

// ---------------- per-dst edge softmax (writes alpha into g_ge) ----------------
__global__ void node_softmax() {
    int w = (blockIdx.x * blockDim.x + threadIdx.x) >> 5;
    if (w >= NN) return;
    int lane = threadIdx.x & 31;
    int s0 = g_indptr[w], s1 = g_indptr[w + 1];
    if (s0 == s1) return;
    float m0 = -FLT_MAX, m1 = -FLT_MAX;
    for (int p = s0 + lane; p < s1; p += 32) {
        int e = g_eids[p];
        m0 = fmaxf(m0, g_ge[e * 2]);
        m1 = fmaxf(m1, g_ge[e * 2 + 1]);
    }
    #pragma unroll
    for (int o = 16; o; o >>= 1) {
        m0 = fmaxf(m0, __shfl_xor_sync(0xffffffffu, m0, o));
        m1 = fmaxf(m1, __shfl_xor_sync(0xffffffffu, m1, o));
    }
    float d0 = 0.f, d1 = 0.f;
    for (int p = s0 + lane; p < s1; p += 32) {
        int e = g_eids[p];
        d0 += expf(g_ge[e * 2] - m0);
        d1 += expf(g_ge[e * 2 + 1] - m1);
    }
    #pragma unroll
    for (int o = 16; o; o >>= 1) {
        d0 += __shfl_xor_sync(0xffffffffu, d0, o);
        d1 += __shfl_xor_sync(0xffffffffu, d1, o);
    }
    float i0 = 1.f / d0, i1 = 1.f / d1;
    for (int p = s0 + lane; p < s1; p += 32) {
        int e = g_eids[p];
        g_ge[e * 2]     = expf(g_ge[e * 2] - m0) * i0;
        g_ge[e * 2 + 1] = expf(g_ge[e * 2 + 1] - m1) * i1;
    }
}

// ---------------- GAT accumulation + bias + relu ----------------
__global__ void gat_accum(const int* __restrict__ src, const float* __restrict__ gbias) {
    int w = (blockIdx.x * blockDim.x + threadIdx.x) >> 5;
    if (w >= NN) return;
    int lane = threadIdx.x & 31;
    int s0 = g_indptr[w], s1 = g_indptr[w + 1];
    float4 a0 = make_float4(0.f, 0.f, 0.f, 0.f);
    float4 a1 = make_float4(0.f, 0.f, 0.f, 0.f);
    for (int p = s0; p < s1; p++) {
        int e = g_eids[p];
        int s = src[e];
        float al0 = g_ge[e * 2], al1 = g_ge[e * 2 + 1];
        const float4* z = (const float4*)(g_zft + (size_t)s * 256);
        float4 z0 = z[lane], z1 = z[32 + lane];
        a0.x += al0 * z0.x; a0.y += al0 * z0.y; a0.z += al0 * z0.z; a0.w += al0 * z0.w;
        a1.x += al1 * z1.x; a1.y += al1 * z1.y; a1.z += al1 * z1.z; a1.w += al1 * z1.w;
    }
    const float4* b4 = (const float4*)gbias;
    float4 b0 = b4[lane], b1 = b4[32 + lane];
    float4 o0, o1;
    o0.x = fmaxf(a0.x + b0.x, 0.f); o0.y = fmaxf(a0.y + b0.y, 0.f);
    o0.z = fmaxf(a0.z + b0.z, 0.f); o0.w = fmaxf(a0.w + b0.w, 0.f);
    o1.x = fmaxf(a1.x + b1.x, 0.f); o1.y = fmaxf(a1.y + b1.y, 0.f);
    o1.z = fmaxf(a1.z + b1.z, 0.f); o1.w = fmaxf(a1.w + b1.w, 0.f);
    float4* outp = (float4*)(g_rst + (size_t)w * 256);
    outp[lane] = o0;
    outp[32 + lane] = o1;
}

// ---------------- graph boundaries via binary search on sorted gid ----------------
__global__ void graph_bounds(const int* __restrict__ gid) {
    int b = threadIdx.x;
    if (b > NG) return;
    if (b == NG) { g_gs[NG] = NN; return; }
    int lo = 0, hi = NN;
    while (lo < hi) {
        int mid = (lo + hi) >> 1;
        if (gid[mid] < b) lo = mid + 1; else hi = mid;
    }
    g_gs[b] = lo;
}

// ---------------- mean pool per graph + classify ----------------
__global__ void pool_classify(const float* __restrict__ Wc, const float* __restrict__ bc, int gidx) {
    __shared__ float sh[256];
    int b = blockIdx.x;
    int t = threadIdx.x;  // 256
    int s = g_gs[b], e2 = g_gs[b + 1];
    float sum = 0.f;
    for (int r = s; r < e2; r++) sum += g_rst[(size_t)r * 256 + t];
    sh[t] = sum / fmaxf((float)(e2 - s), 1.f);
    __syncthreads();
    if (t < 64) {
        int hd = t >> 5, c = t & 31;
        float acc = bc[c];
        const float* hp = sh + hd * 128;
        const float* wp = Wc + c * 128;
        #pragma unroll 8
        for (int d2 = 0; d2 < 128; d2++) acc += hp[d2] * wp[d2];
        g_logits[gidx][(b * 2 + hd) * 32 + c] = acc;
    }
}

// ---------------- final distance + head softmax ----------------
__global__ void final_kernel(float* __restrict__ out) {
    int b = threadIdx.x;
    if (b >= NG) return;
    float dv[2];
    #pragma unroll
    for (int hd = 0; hd < 2; hd++) {
        float ss = 0.f;
        #pragma unroll
        for (int c = 0; c < 32; c++) {
            float df = g_logits[0][(b * 2 + hd) * 32 + c]
                     - g_logits[1][(b * 2 + hd) * 32 + c] + 1e-6f;
            ss += df * df;
        }
        dv[hd] = sqrtf(ss);
    }
    float mx = fmaxf(dv[0], dv[1]);
    float e0 = expf(dv[0] - mx), e1 = expf(dv[1] - mx);
    float inv = 1.f / (e0 + e1);
    out[b * 2] = e0 * inv;
    out[b * 2 + 1] = e1 * inv;
}

// ---------------- host driver ----------------
extern "C" void kernel_launch(void* const* d_in, const int* in_sizes, int n_in,
                              void* d_out, int out_size) {
    const float* in1  = (const float*)d_in[0];
    const float* in2  = (const float*)d_in[1];
    const int* src1 = (const int*)d_in[2];
    const int* dst1 = (const int*)d_in[3];
    const int* et1  = (const int*)d_in[4];
    const int* gid1 = (const int*)d_in[5];
    const int* src2 = (const int*)d_in[6];
    const int* dst2 = (const int*)d_in[7];
    const int* et2  = (const int*)d_in[8];
    const int* gid2 = (const int*)d_in[9];
    const float* W_et  = (const float*)d_in[10];
    const float* b_et  = (const float*)d_in[11];
    const float* W_ih  = (const float*)d_in[12];
    const float* W_hh  = (const float*)d_in[13];
    const float* b_ih  = (const float*)d_in[14];
    const float* b_hh  = (const float*)d_in[15];
    const float* W_fc  = (const float*)d_in[16];
    const float* al    = (const float*)d_in[17];
    const float* ar    = (const float*)d_in[18];
    const float* gb    = (const float*)d_in[19];
    const float* W_cls = (const float*)d_in[20];
    const float* b_cls = (const float*)d_in[21];

    const int NBLK_E = (NE + 255) / 256;
    const int NBLK_N = (NN + 255) / 256;
    const int NBLK_W = NN / 8;              // warp-per-node, 8 warps/block
    const dim3 gT(391, 4), g3(391, 3), g2d(391, 2);

    for (int g = 0; g < 2; g++) {
        const float* feat = g ? in2 : in1;
        const int* src = g ? src2 : src1;
        const int* dst = g ? dst2 : dst1;
        const int* et  = g ? et2 : et1;
        const int* gid = g ? gid2 : gid1;

        copy_h<<<(NN * 32 + 255) / 256, 256>>>(feat);
        zero_deg<<<NBLK_N, 256>>>();
        count_deg<<<NBLK_E, 256>>>(dst);
        scan_deg<<<1, 1024>>>();
        build_eids<<<NBLK_E, 256>>>(dst);

        for (int s = 0; s < NSTEPS; s++) {
            gemm_tf32<<<gT, 256>>>(0, W_et, b_et, 0, 512);   // t = h @ W_et^T + b_et
            gemm_tf32<<<g3, 256>>>(0, W_hh, b_hh, 1, 384);   // gh = h @ W_hh^T + b_hh
            aggregate<<<NBLK_W, 256>>>(src, et);             // a = segment_sum msg
            gemm_tf32<<<g3, 256>>>(1, W_ih, b_ih, 2, 384);   // gi = a @ W_ih^T + b_ih
            gru_update<<<(NN * 32 + 255) / 256, 256>>>();
        }
        norm_sigmoid<<<NBLK_W, 256>>>();
        gemm_tf32<<<g2d, 256>>>(0, W_fc, nullptr, 3, 256);   // zft
        elr_kernel<<<NBLK_W, 256>>>(al, ar);
        edge_e<<<NBLK_E, 256>>>(src, dst);
        node_softmax<<<NBLK_W, 256>>>();
        gat_accum<<<NBLK_W, 256>>>(src, gb);
        graph_bounds<<<1, NG + 1>>>(gid);
        pool_classify<<<NG, 256>>>(W_cls, b_cls, g);
    }
    final_kernel<<<1, NG>>>((float*)d_out);
}

// round 3
// speedup vs baseline: 3.5569x; 1.1481x over previous
#include <cuda_runtime.h>
#include <cuda_fp16.h>
#include <math.h>
#include <float.h>

// ---------------- problem constants ----------------
#define NN      50000
#define NE      600000
#define DD      128
#define NET     4
#define NSTEPS  5
#define NHEADS  2
#define NG      64
#define NCLS    32

// ---------------- device scratch ----------------
__device__ float  g_h  [NN * DD];                 // node state (fp32)
__device__ float  g_a  [NN * DD];                 // aggregated messages (fp32)
__device__ __half g_t_h  [(size_t)NN * NET * DD]; // per-etype transform (fp16)
__device__ __half g_gh_h [NN * 3 * DD];           // GRU hidden gates (fp16)
__device__ __half g_gi_h [NN * 3 * DD];           // GRU input gates (fp16)
__device__ __half g_zft_h[NN * NHEADS * DD];      // GAT features (fp16)
__device__ float  g_el [NN * NHEADS];
__device__ float  g_er [NN * NHEADS];
__device__ float  g_ge [NE * NHEADS];
__device__ float  g_rst[NN * NHEADS * DD];
__device__ float  g_logits[2][NG * NHEADS * NCLS];

__device__ int g_deg   [NN];
__device__ int g_indptr[NN + 1];
__device__ int g_cursor[NN];
__device__ int g_eids  [NE];
__device__ int g_gs    [NG + 1];
__device__ int g_bsum  [64];

__device__ __forceinline__ float sigf(float x) { return 1.f / (1.f + expf(-x)); }

__device__ __forceinline__ float4 h4tof4(uint2 v) {
    float2 a = __half22float2(*(__half2*)&v.x);
    float2 b = __half22float2(*(__half2*)&v.y);
    return make_float4(a.x, a.y, b.x, b.y);
}

// ---------------- misc small kernels ----------------
__global__ void copy_h(const float* __restrict__ f) {
    int i = blockIdx.x * blockDim.x + threadIdx.x;
    if (i < NN * (DD / 4)) ((float4*)g_h)[i] = ((const float4*)f)[i];
}

__global__ void zero_deg() {
    int i = blockIdx.x * blockDim.x + threadIdx.x;
    if (i < NN) g_deg[i] = 0;
}

__global__ void count_deg(const int* __restrict__ dst) {
    int e = blockIdx.x * blockDim.x + threadIdx.x;
    if (e < NE) atomicAdd(&g_deg[dst[e]], 1);
}

// ---- multi-block scan: 49 blocks x 1024 ----
__global__ void scan1() {
    __shared__ int wsum[32];
    int tid = threadIdx.x;
    int i = blockIdx.x * 1024 + tid;
    int v = (i < NN) ? g_deg[i] : 0;
    int x = v;
    #pragma unroll
    for (int o = 1; o < 32; o <<= 1) {
        int y = __shfl_up_sync(0xffffffffu, x, o);
        if ((tid & 31) >= o) x += y;
    }
    if ((tid & 31) == 31) wsum[tid >> 5] = x;
    __syncthreads();
    if (tid < 32) {
        int wv = wsum[tid];
        int xs = wv;
        #pragma unroll
        for (int o = 1; o < 32; o <<= 1) {
            int y = __shfl_up_sync(0xffffffffu, xs, o);
            if (tid >= o) xs += y;
        }
        wsum[tid] = xs - wv;  // exclusive
    }
    __syncthreads();
    int excl = (x - v) + wsum[tid >> 5];
    if (i < NN) g_indptr[i] = excl;
    if (tid == 1023) g_bsum[blockIdx.x] = excl + v;
}

__global__ void scan2() {
    int s = 0;
    for (int b = 0; b < 49; b++) { int t = g_bsum[b]; g_bsum[b] = s; s += t; }
    g_indptr[NN] = s;
}

__global__ void scan3() {
    int i = blockIdx.x * 1024 + threadIdx.x;
    if (i < NN) {
        int v = g_indptr[i] + g_bsum[blockIdx.x];
        g_indptr[i] = v;
        g_cursor[i] = v;
    }
}

__global__ void build_eids(const int* __restrict__ dst) {
    int e = blockIdx.x * blockDim.x + threadIdx.x;
    if (e < NE) {
        int p = atomicAdd(&g_cursor[dst[e]], 1);
        g_eids[p] = e;
    }
}

// ---------------- TF32 tensor-core GEMM core ----------------
// C(half)[n, col] = sum_d A[n,d]*Bw[col,d] + bias[col]
// Block 128x128 tile, K=128 in 4 chunks of 32, cp.async 2-stage pipeline.
#define SPAD 36
#define STG  (128 * SPAD)

__device__ __forceinline__ void gemm_body(
    const float* __restrict__ A, const float* __restrict__ Bw,
    const float* __restrict__ bias, __half* __restrict__ C,
    int outDim, int rowBase, int colBase,
    unsigned* As, unsigned* Bs)
{
    const int tid = threadIdx.x;
    const int lane = tid & 31, wid = tid >> 5;
    const int wm = wid >> 2, wn = wid & 3;
    const int g8 = lane >> 2, t4 = lane & 3;
    const int lr = tid >> 1, lh = (tid & 1) * 16;

    float c[4][4][4];
    #pragma unroll
    for (int mt = 0; mt < 4; mt++)
        #pragma unroll
        for (int nt = 0; nt < 4; nt++)
            #pragma unroll
            for (int i = 0; i < 4; i++) c[mt][nt][i] = 0.f;

    const int ga = rowBase + lr;
    const float* Ap = A + (size_t)ga * 128 + lh;
    const float* Bp = Bw + (size_t)(colBase + lr) * 128 + lh;
    const int aBytes = (ga < NN) ? 16 : 0;
    const unsigned aDst = (unsigned)__cvta_generic_to_shared(&As[lr * SPAD + lh]);
    const unsigned bDst = (unsigned)__cvta_generic_to_shared(&Bs[lr * SPAD + lh]);

    // stage chunk kc into buffer s
    #define STAGE(s, kc)                                                          \
        do {                                                                      \
            _Pragma("unroll")                                                     \
            for (int i = 0; i < 4; i++) {                                         \
                asm volatile("cp.async.cg.shared.global [%0], [%1], 16, %2;"      \
                    :: "r"(aDst + (s) * (STG * 4) + i * 16),                      \
                       "l"(Ap + (kc) + i * 4), "r"(aBytes));                      \
                asm volatile("cp.async.cg.shared.global [%0], [%1], 16;"          \
                    :: "r"(bDst + (s) * (STG * 4) + i * 16),                      \
                       "l"(Bp + (kc) + i * 4));                                   \
            }                                                                     \
            asm volatile("cp.async.commit_group;");                               \
        } while (0)

    STAGE(0, 0);
    #pragma unroll
    for (int kc4 = 0; kc4 < 4; kc4++) {
        if (kc4 < 3) {
            STAGE((kc4 + 1) & 1, (kc4 + 1) * 32);
            asm volatile("cp.async.wait_group 1;");
        } else {
            asm volatile("cp.async.wait_group 0;");
        }
        __syncthreads();
        const unsigned* Ab = As + (kc4 & 1) * STG;
        const unsigned* Bb = Bs + (kc4 & 1) * STG;
        #pragma unroll
        for (int k8 = 0; k8 < 4; k8++) {
            const int kb = k8 * 8;
            unsigned af[4][4], bf[4][2];
            #pragma unroll
            for (int mt = 0; mt < 4; mt++) {
                int r0 = wm * 64 + mt * 16 + g8;
                af[mt][0] = Ab[r0 * SPAD + kb + t4];
                af[mt][1] = Ab[(r0 + 8) * SPAD + kb + t4];
                af[mt][2] = Ab[r0 * SPAD + kb + t4 + 4];
                af[mt][3] = Ab[(r0 + 8) * SPAD + kb + t4 + 4];
            }
            #pragma unroll
            for (int nt = 0; nt < 4; nt++) {
                int n0 = wn * 32 + nt * 8 + g8;
                bf[nt][0] = Bb[n0 * SPAD + kb + t4];
                bf[nt][1] = Bb[n0 * SPAD + kb + t4 + 4];
            }
            #pragma unroll
            for (int mt = 0; mt < 4; mt++)
                #pragma unroll
                for (int nt = 0; nt < 4; nt++) {
                    asm volatile(
                        "mma.sync.aligned.m16n8k8.row.col.f32.tf32.tf32.f32 "
                        "{%0,%1,%2,%3}, {%4,%5,%6,%7}, {%8,%9}, {%0,%1,%2,%3};\n"
                        : "+f"(c[mt][nt][0]), "+f"(c[mt][nt][1]),
                          "+f"(c[mt][nt][2]), "+f"(c[mt][nt][3])
                        : "r"(af[mt][0]), "r"(af[mt][1]), "r"(af[mt][2]), "r"(af[mt][3]),
                          "r"(bf[nt][0]), "r"(bf[nt][1]));
                }
        }
        __syncthreads();
    }
    #undef STAGE

    // epilogue: bias + fp16 store
    #pragma unroll
    for (int mt = 0; mt < 4; mt++) {
        int r0 = rowBase + wm * 64 + mt * 16 + g8;
        #pragma unroll
        for (int nt = 0; nt < 4; nt++) {
            int col = colBase + wn * 32 + nt * 8 + 2 * t4;
            float b0 = bias ? bias[col] : 0.f;
            float b1 = bias ? bias[col + 1] : 0.f;
            if (r0 < NN)
                *(__half2*)(C + (size_t)r0 * outDim + col) =
                    __floats2half2_rn(c[mt][nt][0] + b0, c[mt][nt][1] + b1);
            if (r0 + 8 < NN)
                *(__half2*)(C + (size_t)(r0 + 8) * outDim + col) =
                    __floats2half2_rn(c[mt][nt][2] + b0, c[mt][nt][3] + b1);
        }
    }
}

// mode 0: fused et (y<4 -> g_t_h) + hh (y>=4 -> g_gh_h), A = g_h
// mode 1: gi (A = g_a, C = g_gi_h)
// mode 2: zft (A = g_h, C = g_zft_h, no bias)
__global__ __launch_bounds__(256, 2)
void gemm_all(int mode, const float* __restrict__ W0, const float* __restrict__ b0,
              const float* __restrict__ W1, const float* __restrict__ b1) {
    extern __shared__ unsigned sm[];
    unsigned* As = sm;
    unsigned* Bs = sm + 2 * STG;
    int y = blockIdx.y;
    const float* A; const float* Bw; const float* bias; __half* C;
    int outDim, colBase;
    if (mode == 0) {
        A = g_h;
        if (y < 4) { Bw = W0; bias = b0; C = g_t_h;  outDim = 512; colBase = y * 128; }
        else       { Bw = W1; bias = b1; C = g_gh_h; outDim = 384; colBase = (y - 4) * 128; }
    } else if (mode == 1) {
        A = g_a; Bw = W0; bias = b0; C = g_gi_h; outDim = 384; colBase = y * 128;
    } else {
        A = g_h; Bw = W0; bias = nullptr; C = g_zft_h; outDim = 256; colBase = y * 128;
    }
    gemm_body(A, Bw, bias, C, outDim, blockIdx.x * 128, colBase, As, Bs);
}

// ---------------- message aggregation (fp16 t -> fp32 a) ----------------
__global__ void aggregate(const int* __restrict__ src, const int* __restrict__ et) {
    int w = (blockIdx.x * blockDim.x + threadIdx.x) >> 5;
    if (w >= NN) return;
    int lane = threadIdx.x & 31;
    int s0 = g_indptr[w], s1 = g_indptr[w + 1];
    float4 acc = make_float4(0.f, 0.f, 0.f, 0.f);
    for (int p = s0; p < s1; p++) {
        int e = g_eids[p];
        int s = src[e];
        int k = et[e];
        uint2 v = ((const uint2*)(g_t_h + (size_t)s * (NET * DD) + k * DD))[lane];
        float4 f = h4tof4(v);
        acc.x += f.x; acc.y += f.y; acc.z += f.z; acc.w += f.w;
    }
    ((float4*)(g_a + (size_t)w * DD))[lane] = acc;
}

// ---------------- GRU elementwise update (fp16 gates) ----------------
__global__ void gru_update() {
    int idx = blockIdx.x * blockDim.x + threadIdx.x;
    if (idx >= NN * 32) return;
    int n = idx >> 5, q = idx & 31;
    const __half* gip = g_gi_h + (size_t)n * 384 + q * 4;
    const __half* ghp = g_gh_h + (size_t)n * 384 + q * 4;
    float4 ir = h4tof4(*(const uint2*)gip);
    float4 iz = h4tof4(*(const uint2*)(gip + 128));
    float4 inn = h4tof4(*(const uint2*)(gip + 256));
    float4 hr = h4tof4(*(const uint2*)ghp);
    float4 hz = h4tof4(*(const uint2*)(ghp + 128));
    float4 hn = h4tof4(*(const uint2*)(ghp + 256));
    float4* hp = (float4*)(g_h + (size_t)n * 128);
    float4 h = hp[q];
    float4 o;
    {
        float r = sigf(ir.x + hr.x), z = sigf(iz.x + hz.x);
        float nn2 = tanhf(inn.x + r * hn.x);
        o.x = (1.f - z) * nn2 + z * h.x;
    }
    {
        float r = sigf(ir.y + hr.y), z = sigf(iz.y + hz.y);
        float nn2 = tanhf(inn.y + r * hn.y);
        o.y = (1.f - z) * nn2 + z * h.y;
    }
    {
        float r = sigf(ir.z + hr.z), z = sigf(iz.z + hz.z);
        float nn2 = tanhf(inn.z + r * hn.z);
        o.z = (1.f - z) * nn2 + z * h.z;
    }
    {
        float r = sigf(ir.w + hr.w), z = sigf(iz.w + hz.w);
        float nn2 = tanhf(inn.w + r * hn.w);
        o.w = (1.f - z) * nn2 + z * h.w;
    }
    hp[q] = o;
}

// ---------------- row L2-normalize + sigmoid ----------------
__global__ void norm_sigmoid() {
    int w = (blockIdx.x * blockDim.x + threadIdx.x) >> 5;
    if (w >= NN) return;
    int lane = threadIdx.x & 31;
    float4* p = (float4*)(g_h + (size_t)w * 128);
    float4 v = p[lane];
    float ss = v.x * v.x + v.y * v.y + v.z * v.z + v.w * v.w;
    #pragma unroll
    for (int o = 16; o; o >>= 1) ss += __shfl_xor_sync(0xffffffffu, ss, o);
    float inv = 1.f / fmaxf(sqrtf(ss), 1e-12f);
    v.x = sigf(v.x * inv); v.y = sigf(v.y * inv);
    v.z = sigf(v.z * inv); v.w = sigf(v.w * inv);
    p[lane] = v;
}

// ---------------- GAT attention scalars el/er per node (fp16 zft) ----------------
__global__ void elr_kernel(const float* __restrict__ al, const float* __restrict__ ar) {
    int w = (blockIdx.x * blockDim.x + threadIdx.x) >> 5;
    if (w >= NN) return;
    int lane = threadIdx.x & 31;
    const uint2* z2 = (const uint2*)(g_zft_h + (size_t)w * 256);
    const float4* al4 = (const float4*)al;
    const float4* ar4 = (const float4*)ar;
    #pragma unroll
    for (int hd = 0; hd < 2; hd++) {
        float4 zv = h4tof4(z2[hd * 32 + lane]);
        float4 lv = al4[hd * 32 + lane];
        float4 rv = ar4[hd * 32 + lane];
        float pl = zv.x * lv.x + zv.y * lv.y + zv.z * lv.z + zv.w * lv.w;
        float pr = zv.x * rv.x + zv.y * rv.y + zv.z * rv.z + zv.w * rv.w;
        #pragma unroll
        for (int o = 16; o; o >>= 1) {
            pl += __shfl_xor_sync(0xffffffffu, pl, o);
            pr += __shfl_xor_sync(0xffffffffu, pr, o);
        }
        if (lane == 0) { g_el[w * 2 + hd] = pl; g_er[w * 2 + hd] = pr; }
    }
}

// ---------------- GAT edge logits ----------------
__global__ void edge_e(const int* __restrict__ src, const int* __restrict__ dst) {
    int e = blockIdx.x * blockDim.x + threadIdx.x;
    if (e >= NE) return;
    int s = src[e], d = dst[e];
    #pragma unroll
    for (int hd = 0; hd < 2; hd++) {
        float x = g_el[s * 2 + hd] + g_er[d * 2 + hd];
        g_ge[e * 2 + hd] = x > 0.f ? x : 0.2f * x;
    }
}

// ---------------- per-dst edge softmax ----------------
__global__ void node_softmax() {
    int w = (blockIdx.x * blockDim.x + threadIdx.x) >> 5;
    if (w >= NN) return;
    int lane = threadIdx.x & 31;
    int s0 = g_indptr[w], s1 = g_indptr[w + 1];
    if (s0 == s1) return;
    float m0 = -FLT_MAX, m1 = -FLT_MAX;
    for (int p = s0 + lane; p < s1; p += 32) {
        int e = g_eids[p];
        m0 = fmaxf(m0, g_ge[e * 2]);
        m1 = fmaxf(m1, g_ge[e * 2 + 1]);
    }
    #pragma unroll
    for (int o = 16; o; o >>= 1) {
        m0 = fmaxf(m0, __shfl_xor_sync(0xffffffffu, m0, o));
        m1 = fmaxf(m1, __shfl_xor_sync(0xffffffffu, m1, o));
    }
    float d0 = 0.f, d1 = 0.f;
    for (int p = s0 + lane; p < s1; p += 32) {
        int e = g_eids[p];
        d0 += expf(g_ge[e * 2] - m0);
        d1 += expf(g_ge[e * 2 + 1] - m1);
    }
    #pragma unroll
    for (int o = 16; o; o >>= 1) {
        d0 += __shfl_xor_sync(0xffffffffu, d0, o);
        d1 += __shfl_xor_sync(0xffffffffu, d1, o);
    }
    float i0 = 1.f / d0, i1 = 1.f / d1;
    for (int p = s0 + lane; p < s1; p += 32) {
        int e = g_eids[p];
        g_ge[e * 2]     = expf(g_ge[e * 2] - m0) * i0;
        g_ge[e * 2 + 1] = expf(g_ge[e * 2 + 1] - m1) * i1;
    }
}

// ---------------- GAT accumulation + bias + relu (fp16 zft) ----------------
__global__ void gat_accum(const int* __restrict__ src, const float* __restrict__ gbias) {
    int w = (blockIdx.x * blockDim.x + threadIdx.x) >> 5;
    if (w >= NN) return;
    int lane = threadIdx.x & 31;
    int s0 = g_indptr[w], s1 = g_indptr[w + 1];
    float4 a0 = make_float4(0.f, 0.f, 0.f, 0.f);
    float4 a1 = make_float4(0.f, 0.f, 0.f, 0.f);
    for (int p = s0; p < s1; p++) {
        int e = g_eids[p];
        int s = src[e];
        float al0 = g_ge[e * 2], al1 = g_ge[e * 2 + 1];
        const uint2* z2 = (const uint2*)(g_zft_h + (size_t)s * 256);
        float4 z0 = h4tof4(z2[lane]), z1 = h4tof4(z2[32 + lane]);
        a0.x += al0 * z0.x; a0.y += al0 * z0.y; a0.z += al0 * z0.z; a0.w += al0 * z0.w;
        a1.x += al1 * z1.x; a1.y += al1 * z1.y; a1.z += al1 * z1.z; a1.w += al1 * z1.w;
    }
    const float4* b4 = (const float4*)gbias;
    float4 b0 = b4[lane], b1 = b4[32 + lane];
    float4 o0, o1;
    o0.x = fmaxf(a0.x + b0.x, 0.f); o0.y = fmaxf(a0.y + b0.y, 0.f);
    o0.z = fmaxf(a0.z + b0.z, 0.f); o0.w = fmaxf(a0.w + b0.w, 0.f);
    o1.x = fmaxf(a1.x + b1.x, 0.f); o1.y = fmaxf(a1.y + b1.y, 0.f);
    o1.z = fmaxf(a1.z + b1.z, 0.f); o1.w = fmaxf(a1.w + b1.w, 0.f);
    float4* outp = (float4*)(g_rst + (size_t)w * 256);
    outp[lane] = o0;
    outp[32 + lane] = o1;
}

// ---------------- graph bounds ----------------
__global__ void graph_bounds(const int* __restrict__ gid) {
    int b = threadIdx.x;
    if (b > NG) return;
    if (b == NG) { g_gs[NG] = NN; return; }
    int lo = 0, hi = NN;
    while (lo < hi) {
        int mid = (lo + hi) >> 1;
        if (gid[mid] < b) lo = mid + 1; else hi = mid;
    }
    g_gs[b] = lo;
}

// ---------------- mean pool + classify ----------------
__global__ void pool_classify(const float* __restrict__ Wc, const float* __restrict__ bc, int gidx) {
    __shared__ float sh[256];
    int b = blockIdx.x;
    int t = threadIdx.x;
    int s = g_gs[b], e2 = g_gs[b + 1];
    float sum = 0.f;
    for (int r = s; r < e2; r++) sum += g_rst[(size_t)r * 256 + t];
    sh[t] = sum / fmaxf((float)(e2 - s), 1.f);
    __syncthreads();
    if (t < 64) {
        int hd = t >> 5, c = t & 31;
        float acc = bc[c];
        const float* hp = sh + hd * 128;
        const float* wp = Wc + c * 128;
        #pragma unroll 8
        for (int d2 = 0; d2 < 128; d2++) acc += hp[d2] * wp[d2];
        g_logits[gidx][(b * 2 + hd) * 32 + c] = acc;
    }
}

// ---------------- final distance + head softmax ----------------
__global__ void final_kernel(float* __restrict__ out) {
    int b = threadIdx.x;
    if (b >= NG) return;
    float dv[2];
    #pragma unroll
    for (int hd = 0; hd < 2; hd++) {
        float ss = 0.f;
        #pragma unroll
        for (int c = 0; c < 32; c++) {
            float df = g_logits[0][(b * 2 + hd) * 32 + c]
                     - g_logits[1][(b * 2 + hd) * 32 + c] + 1e-6f;
            ss += df * df;
        }
        dv[hd] = sqrtf(ss);
    }
    float mx = fmaxf(dv[0], dv[1]);
    float e0 = expf(dv[0] - mx), e1 = expf(dv[1] - mx);
    float inv = 1.f / (e0 + e1);
    out[b * 2] = e0 * inv;
    out[b * 2 + 1] = e1 * inv;
}

// ---------------- host driver ----------------
extern "C" void kernel_launch(void* const* d_in, const int* in_sizes, int n_in,
                              void* d_out, int out_size) {
    const float* in1  = (const float*)d_in[0];
    const float* in2  = (const float*)d_in[1];
    const int* src1 = (const int*)d_in[2];
    const int* dst1 = (const int*)d_in[3];
    const int* et1  = (const int*)d_in[4];
    const int* gid1 = (const int*)d_in[5];
    const int* src2 = (const int*)d_in[6];
    const int* dst2 = (const int*)d_in[7];
    const int* et2  = (const int*)d_in[8];
    const int* gid2 = (const int*)d_in[9];
    const float* W_et  = (const float*)d_in[10];
    const float* b_et  = (const float*)d_in[11];
    const float* W_ih  = (const float*)d_in[12];
    const float* W_hh  = (const float*)d_in[13];
    const float* b_ih  = (const float*)d_in[14];
    const float* b_hh  = (const float*)d_in[15];
    const float* W_fc  = (const float*)d_in[16];
    const float* al    = (const float*)d_in[17];
    const float* ar    = (const float*)d_in[18];
    const float* gb    = (const float*)d_in[19];
    const float* W_cls = (const float*)d_in[20];
    const float* b_cls = (const float*)d_in[21];

    const int SMEM = 4 * STG * 4;  // 2 stages x (A+B) x 128*36 words
    static int attr_done = 0;
    if (!attr_done) {
        cudaFuncSetAttribute(gemm_all, cudaFuncAttributeMaxDynamicSharedMemorySize, SMEM);
        attr_done = 1;
    }

    const int NBLK_E = (NE + 255) / 256;
    const int NBLK_N = (NN + 255) / 256;
    const int NBLK_W = NN / 8;
    const dim3 gFused(391, 7), gGI(391, 3), gZ(391, 2);

    for (int g = 0; g < 2; g++) {
        const float* feat = g ? in2 : in1;
        const int* src = g ? src2 : src1;
        const int* dst = g ? dst2 : dst1;
        const int* et  = g ? et2 : et1;
        const int* gid = g ? gid2 : gid1;

        copy_h<<<(NN * 32 + 255) / 256, 256>>>(feat);
        zero_deg<<<NBLK_N, 256>>>();
        count_deg<<<NBLK_E, 256>>>(dst);
        scan1<<<49, 1024>>>();
        scan2<<<1, 1>>>();
        scan3<<<49, 1024>>>();
        build_eids<<<NBLK_E, 256>>>(dst);

        for (int s = 0; s < NSTEPS; s++) {
            gemm_all<<<gFused, 256, SMEM>>>(0, W_et, b_et, W_hh, b_hh);
            aggregate<<<NBLK_W, 256>>>(src, et);
            gemm_all<<<gGI, 256, SMEM>>>(1, W_ih, b_ih, nullptr, nullptr);
            gru_update<<<(NN * 32 + 255) / 256, 256>>>();
        }
        norm_sigmoid<<<NBLK_W, 256>>>();
        gemm_all<<<gZ, 256, SMEM>>>(2, W_fc, nullptr, nullptr, nullptr);
        elr_kernel<<<NBLK_W, 256>>>(al, ar);
        edge_e<<<NBLK_E, 256>>>(src, dst);
        node_softmax<<<NBLK_W, 256>>>();
        gat_accum<<<NBLK_W, 256>>>(src, gb);
        graph_bounds<<<1, NG + 1>>>(gid);
        pool_classify<<<NG, 256>>>(W_cls, b_cls, g);
    }
    final_kernel<<<1, NG>>>((float*)d_out);
}

// round 5
// speedup vs baseline: 4.6391x; 1.3042x over previous
#include <cuda_runtime.h>
#include <cuda_fp16.h>
#include <math.h>
#include <float.h>

// ---------------- problem constants ----------------
#define NN      50000
#define NE      600000
#define DD      128
#define NET     4
#define NSTEPS  5
#define NHEADS  2
#define NG      64
#define NCLS    32

// ---------------- device scratch ----------------
__device__ float  g_h  [NN * DD];                 // node state master (fp32)
__device__ __half g_h_h[NN * DD];                 // fp16 mirror for GEMM A
__device__ __half g_a_h[NN * DD];                 // aggregated messages (fp16)
__device__ __half g_t_h  [(size_t)NN * NET * DD]; // per-etype transform (fp16)
__device__ __half g_gh_h [NN * 3 * DD];           // GRU hidden gates (fp16)
__device__ __half g_gi_h [NN * 3 * DD];           // GRU input gates (fp16)
__device__ __half g_zft_h[NN * NHEADS * DD];      // GAT features (fp16)
__device__ float  g_el [NN * NHEADS];
__device__ float  g_er [NN * NHEADS];
__device__ float  g_ge [NE * NHEADS];
__device__ float  g_rst[NN * NHEADS * DD];
__device__ float  g_logits[2][NG * NHEADS * NCLS];

// fp16 weights (converted once per launch)
__device__ __half g_Wet_h[NET * DD * DD];   // 65536
__device__ __half g_Whh_h[3 * DD * DD];     // 49152
__device__ __half g_Wih_h[3 * DD * DD];
__device__ __half g_Wfc_h[NHEADS * DD * DD];// 32768

__device__ int g_deg   [NN];
__device__ int g_indptr[NN + 1];
__device__ int g_cursor[NN];
__device__ int g_eids  [NE];
__device__ int g_gs    [NG + 1];
__device__ int g_bsum  [64];

__device__ __forceinline__ float sigf(float x) { return 1.f / (1.f + expf(-x)); }

__device__ __forceinline__ float4 h4tof4(uint2 v) {
    float2 a = __half22float2(*(__half2*)&v.x);
    float2 b = __half22float2(*(__half2*)&v.y);
    return make_float4(a.x, a.y, b.x, b.y);
}

// ---------------- misc small kernels ----------------
__global__ void conv_w(const float* __restrict__ src, __half* __restrict__ dst, int n) {
    int i = blockIdx.x * blockDim.x + threadIdx.x;
    if (i < n / 2) {
        float2 v = ((const float2*)src)[i];
        ((__half2*)dst)[i] = __floats2half2_rn(v.x, v.y);
    }
}

__global__ void copy_h(const float* __restrict__ f) {
    int i = blockIdx.x * blockDim.x + threadIdx.x;
    if (i < NN * (DD / 4)) {
        float4 v = ((const float4*)f)[i];
        ((float4*)g_h)[i] = v;
        uint2 h2;
        *(__half2*)&h2.x = __floats2half2_rn(v.x, v.y);
        *(__half2*)&h2.y = __floats2half2_rn(v.z, v.w);
        ((uint2*)g_h_h)[i] = h2;
    }
}

__global__ void zero_deg() {
    int i = blockIdx.x * blockDim.x + threadIdx.x;
    if (i < NN) g_deg[i] = 0;
}

__global__ void count_deg(const int* __restrict__ dst) {
    int e = blockIdx.x * blockDim.x + threadIdx.x;
    if (e < NE) atomicAdd(&g_deg[dst[e]], 1);
}

// ---- multi-block scan: 49 blocks x 1024 ----
__global__ void scan1() {
    __shared__ int wsum[32];
    int tid = threadIdx.x;
    int i = blockIdx.x * 1024 + tid;
    int v = (i < NN) ? g_deg[i] : 0;
    int x = v;
    #pragma unroll
    for (int o = 1; o < 32; o <<= 1) {
        int y = __shfl_up_sync(0xffffffffu, x, o);
        if ((tid & 31) >= o) x += y;
    }
    if ((tid & 31) == 31) wsum[tid >> 5] = x;
    __syncthreads();
    if (tid < 32) {
        int wv = wsum[tid];
        int xs = wv;
        #pragma unroll
        for (int o = 1; o < 32; o <<= 1) {
            int y = __shfl_up_sync(0xffffffffu, xs, o);
            if (tid >= o) xs += y;
        }
        wsum[tid] = xs - wv;
    }
    __syncthreads();
    int excl = (x - v) + wsum[tid >> 5];
    if (i < NN) g_indptr[i] = excl;
    if (tid == 1023) g_bsum[blockIdx.x] = excl + v;
}

__global__ void scan2() {
    int s = 0;
    for (int b = 0; b < 49; b++) { int t = g_bsum[b]; g_bsum[b] = s; s += t; }
    g_indptr[NN] = s;
}

__global__ void scan3() {
    int i = blockIdx.x * 1024 + threadIdx.x;
    if (i < NN) {
        int v = g_indptr[i] + g_bsum[blockIdx.x];
        g_indptr[i] = v;
        g_cursor[i] = v;
    }
}

__global__ void build_eids(const int* __restrict__ dst) {
    int e = blockIdx.x * blockDim.x + threadIdx.x;
    if (e < NE) {
        int p = atomicAdd(&g_cursor[dst[e]], 1);
        g_eids[p] = e;
    }
}

// ---------------- FP16 tensor-core GEMM ----------------
// C(half)[n, col] = sum_d A[n,d]*Bw[col,d] + bias[col]; A,Bw fp16, fp32 accum.
// Block 128x128 tile, full K=128 staged once (2 commit chunks), m16n8k16 mma.
#define S2 68    // half2 row stride (64 data + 4 pad) -> conflict-free frag loads
#define TILE_H2 (128 * S2)

__device__ __forceinline__ void gemm_body(
    const __half* __restrict__ A, const __half* __restrict__ Bw,
    const float* __restrict__ bias, __half* __restrict__ C,
    int outDim, int rowBase, int colBase, __half2* As2, __half2* Bs2)
{
    const int tid = threadIdx.x;
    const int lane = tid & 31, wid = tid >> 5;
    const int wm = wid >> 2, wn = wid & 3;      // 2 x 4 warp grid -> 64x32 per warp
    const int g8 = lane >> 2, t4 = lane & 3;

    float c[4][4][4];
    #pragma unroll
    for (int mt = 0; mt < 4; mt++)
        #pragma unroll
        for (int nt = 0; nt < 4; nt++)
            #pragma unroll
            for (int i = 0; i < 4; i++) c[mt][nt][i] = 0.f;

    // staging: 256 threads; per chunk (32 half2-wide) each thread does 4x16B for A and B
    const int lr = tid >> 1;            // row 0..127
    const int lh2 = (tid & 1) * 16;     // half2 offset within chunk
    const int ga = rowBase + lr;
    const int aBytes = (ga < NN) ? 16 : 0;
    const __half* Ap = A + (size_t)ga * 128;
    const __half* Bp = Bw + (size_t)(colBase + lr) * 128;
    const unsigned aDst = (unsigned)__cvta_generic_to_shared(&As2[lr * S2 + lh2]);
    const unsigned bDst = (unsigned)__cvta_generic_to_shared(&Bs2[lr * S2 + lh2]);

    #pragma unroll
    for (int ch = 0; ch < 2; ch++) {
        #pragma unroll
        for (int i = 0; i < 4; i++) {
            asm volatile("cp.async.cg.shared.global [%0], [%1], 16, %2;"
                :: "r"(aDst + ch * 128 + i * 16),
                   "l"(Ap + ch * 64 + lh2 * 2 + i * 8), "r"(aBytes));
            asm volatile("cp.async.cg.shared.global [%0], [%1], 16;"
                :: "r"(bDst + ch * 128 + i * 16),
                   "l"(Bp + ch * 64 + lh2 * 2 + i * 8));
        }
        asm volatile("cp.async.commit_group;");
    }

    #pragma unroll
    for (int ch = 0; ch < 2; ch++) {
        if (ch == 0) asm volatile("cp.async.wait_group 1;");
        else         asm volatile("cp.async.wait_group 0;");
        __syncthreads();
        #pragma unroll
        for (int ks = 0; ks < 4; ks++) {
            const int kb = ch * 32 + ks * 8;   // half2 units
            unsigned af[4][4], bf[4][2];
            #pragma unroll
            for (int mt = 0; mt < 4; mt++) {
                int r0 = wm * 64 + mt * 16 + g8;
                af[mt][0] = *(unsigned*)&As2[r0 * S2 + kb + t4];
                af[mt][1] = *(unsigned*)&As2[(r0 + 8) * S2 + kb + t4];
                af[mt][2] = *(unsigned*)&As2[r0 * S2 + kb + 4 + t4];
                af[mt][3] = *(unsigned*)&As2[(r0 + 8) * S2 + kb + 4 + t4];
            }
            #pragma unroll
            for (int nt = 0; nt < 4; nt++) {
                int n0 = wn * 32 + nt * 8 + g8;
                bf[nt][0] = *(unsigned*)&Bs2[n0 * S2 + kb + t4];
                bf[nt][1] = *(unsigned*)&Bs2[n0 * S2 + kb + 4 + t4];
            }
            #pragma unroll
            for (int mt = 0; mt < 4; mt++)
                #pragma unroll
                for (int nt = 0; nt < 4; nt++) {
                    asm volatile(
                        "mma.sync.aligned.m16n8k16.row.col.f32.f16.f16.f32 "
                        "{%0,%1,%2,%3}, {%4,%5,%6,%7}, {%8,%9}, {%0,%1,%2,%3};\n"
                        : "+f"(c[mt][nt][0]), "+f"(c[mt][nt][1]),
                          "+f"(c[mt][nt][2]), "+f"(c[mt][nt][3])
                        : "r"(af[mt][0]), "r"(af[mt][1]), "r"(af[mt][2]), "r"(af[mt][3]),
                          "r"(bf[nt][0]), "r"(bf[nt][1]));
                }
        }
    }

    // epilogue: bias + fp16 store
    #pragma unroll
    for (int mt = 0; mt < 4; mt++) {
        int r0 = rowBase + wm * 64 + mt * 16 + g8;
        #pragma unroll
        for (int nt = 0; nt < 4; nt++) {
            int col = colBase + wn * 32 + nt * 8 + 2 * t4;
            float b0 = bias ? bias[col] : 0.f;
            float b1 = bias ? bias[col + 1] : 0.f;
            if (r0 < NN)
                *(__half2*)(C + (size_t)r0 * outDim + col) =
                    __floats2half2_rn(c[mt][nt][0] + b0, c[mt][nt][1] + b1);
            if (r0 + 8 < NN)
                *(__half2*)(C + (size_t)(r0 + 8) * outDim + col) =
                    __floats2half2_rn(c[mt][nt][2] + b0, c[mt][nt][3] + b1);
        }
    }
}

// mode 0: fused et (y<4 -> g_t_h) + hh (y>=4 -> g_gh_h), A = g_h_h
// mode 1: gi (A = g_a_h, C = g_gi_h)
// mode 2: zft (A = g_h_h, C = g_zft_h, no bias)
__global__ __launch_bounds__(256, 2)
void gemm_all(int mode, const float* __restrict__ b0, const float* __restrict__ b1) {
    extern __shared__ __half2 sm2[];
    __half2* As2 = sm2;
    __half2* Bs2 = sm2 + TILE_H2;
    int y = blockIdx.y;
    const __half* A; const __half* Bw; const float* bias; __half* C;
    int outDim, colBase;
    if (mode == 0) {
        A = g_h_h;
        if (y < 4) { Bw = g_Wet_h; bias = b0; C = g_t_h;  outDim = 512; colBase = y * 128; }
        else       { Bw = g_Whh_h; bias = b1; C = g_gh_h; outDim = 384; colBase = (y - 4) * 128; }
    } else if (mode == 1) {
        A = g_a_h; Bw = g_Wih_h; bias = b0; C = g_gi_h; outDim = 384; colBase = y * 128;
    } else {
        A = g_h_h; Bw = g_Wfc_h; bias = nullptr; C = g_zft_h; outDim = 256; colBase = y * 128;
    }
    gemm_body(A, Bw, bias, C, outDim, blockIdx.x * 128, colBase, As2, Bs2);
}

// ---------------- message aggregation (fp16 t -> fp32 acc -> fp16 a) ----------------
__global__ void aggregate(const int* __restrict__ src, const int* __restrict__ et) {
    int w = (blockIdx.x * blockDim.x + threadIdx.x) >> 5;
    if (w >= NN) return;
    int lane = threadIdx.x & 31;
    int s0 = g_indptr[w], s1 = g_indptr[w + 1];
    float4 acc = make_float4(0.f, 0.f, 0.f, 0.f);
    for (int p = s0; p < s1; p++) {
        int e = g_eids[p];
        int s = src[e];
        int k = et[e];
        uint2 v = ((const uint2*)(g_t_h + (size_t)s * (NET * DD) + k * DD))[lane];
        float4 f = h4tof4(v);
        acc.x += f.x; acc.y += f.y; acc.z += f.z; acc.w += f.w;
    }
    uint2 o;
    *(__half2*)&o.x = __floats2half2_rn(acc.x, acc.y);
    *(__half2*)&o.y = __floats2half2_rn(acc.z, acc.w);
    ((uint2*)(g_a_h + (size_t)w * DD))[lane] = o;
}

// ---------------- GRU elementwise update (fp16 gates; writes fp32 h + fp16 mirror) ----------------
__global__ void gru_update() {
    int idx = blockIdx.x * blockDim.x + threadIdx.x;
    if (idx >= NN * 32) return;
    int n = idx >> 5, q = idx & 31;
    const __half* gip = g_gi_h + (size_t)n * 384 + q * 4;
    const __half* ghp = g_gh_h + (size_t)n * 384 + q * 4;
    float4 ir = h4tof4(*(const uint2*)gip);
    float4 iz = h4tof4(*(const uint2*)(gip + 128));
    float4 inn = h4tof4(*(const uint2*)(gip + 256));
    float4 hr = h4tof4(*(const uint2*)ghp);
    float4 hz = h4tof4(*(const uint2*)(ghp + 128));
    float4 hn = h4tof4(*(const uint2*)(ghp + 256));
    float4* hp = (float4*)(g_h + (size_t)n * 128);
    float4 h = hp[q];
    float4 o;
    {
        float r = sigf(ir.x + hr.x), z = sigf(iz.x + hz.x);
        float nn2 = tanhf(inn.x + r * hn.x);
        o.x = (1.f - z) * nn2 + z * h.x;
    }
    {
        float r = sigf(ir.y + hr.y), z = sigf(iz.y + hz.y);
        float nn2 = tanhf(inn.y + r * hn.y);
        o.y = (1.f - z) * nn2 + z * h.y;
    }
    {
        float r = sigf(ir.z + hr.z), z = sigf(iz.z + hz.z);
        float nn2 = tanhf(inn.z + r * hn.z);
        o.z = (1.f - z) * nn2 + z * h.z;
    }
    {
        float r = sigf(ir.w + hr.w), z = sigf(iz.w + hz.w);
        float nn2 = tanhf(inn.w + r * hn.w);
        o.w = (1.f - z) * nn2 + z * h.w;
    }
    hp[q] = o;
    uint2 m;
    *(__half2*)&m.x = __floats2half2_rn(o.x, o.y);
    *(__half2*)&m.y = __floats2half2_rn(o.z, o.w);
    ((uint2*)(g_h_h + (size_t)n * 128))[q] = m;
}

// ---------------- row L2-normalize + sigmoid (updates fp32 + fp16 mirror) ----------------
__global__ void norm_sigmoid() {
    int w = (blockIdx.x * blockDim.x + threadIdx.x) >> 5;
    if (w >= NN) return;
    int lane = threadIdx.x & 31;
    float4* p = (float4*)(g_h + (size_t)w * 128);
    float4 v = p[lane];
    float ss = v.x * v.x + v.y * v.y + v.z * v.z + v.w * v.w;
    #pragma unroll
    for (int o = 16; o; o >>= 1) ss += __shfl_xor_sync(0xffffffffu, ss, o);
    float inv = 1.f / fmaxf(sqrtf(ss), 1e-12f);
    v.x = sigf(v.x * inv); v.y = sigf(v.y * inv);
    v.z = sigf(v.z * inv); v.w = sigf(v.w * inv);
    p[lane] = v;
    uint2 m;
    *(__half2*)&m.x = __floats2half2_rn(v.x, v.y);
    *(__half2*)&m.y = __floats2half2_rn(v.z, v.w);
    ((uint2*)(g_h_h + (size_t)w * 128))[lane] = m;
}

// ---------------- GAT attention scalars el/er ----------------
__global__ void elr_kernel(const float* __restrict__ al, const float* __restrict__ ar) {
    int w = (blockIdx.x * blockDim.x + threadIdx.x) >> 5;
    if (w >= NN) return;
    int lane = threadIdx.x & 31;
    const uint2* z2 = (const uint2*)(g_zft_h + (size_t)w * 256);
    const float4* al4 = (const float4*)al;
    const float4* ar4 = (const float4*)ar;
    #pragma unroll
    for (int hd = 0; hd < 2; hd++) {
        float4 zv = h4tof4(z2[hd * 32 + lane]);
        float4 lv = al4[hd * 32 + lane];
        float4 rv = ar4[hd * 32 + lane];
        float pl = zv.x * lv.x + zv.y * lv.y + zv.z * lv.z + zv.w * lv.w;
        float pr = zv.x * rv.x + zv.y * rv.y + zv.z * rv.z + zv.w * rv.w;
        #pragma unroll
        for (int o = 16; o; o >>= 1) {
            pl += __shfl_xor_sync(0xffffffffu, pl, o);
            pr += __shfl_xor_sync(0xffffffffu, pr, o);
        }
        if (lane == 0) { g_el[w * 2 + hd] = pl; g_er[w * 2 + hd] = pr; }
    }
}

// ---------------- GAT edge logits ----------------
__global__ void edge_e(const int* __restrict__ src, const int* __restrict__ dst) {
    int e = blockIdx.x * blockDim.x + threadIdx.x;
    if (e >= NE) return;
    int s = src[e], d = dst[e];
    #pragma unroll
    for (int hd = 0; hd < 2; hd++) {
        float x = g_el[s * 2 + hd] + g_er[d * 2 + hd];
        g_ge[e * 2 + hd] = x > 0.f ? x : 0.2f * x;
    }
}

// ---------------- per-dst edge softmax ----------------
__global__ void node_softmax() {
    int w = (blockIdx.x * blockDim.x + threadIdx.x) >> 5;
    if (w >= NN) return;
    int lane = threadIdx.x & 31;
    int s0 = g_indptr[w], s1 = g_indptr[w + 1];
    if (s0 == s1) return;
    float m0 = -FLT_MAX, m1 = -FLT_MAX;
    for (int p = s0 + lane; p < s1; p += 32) {
        int e = g_eids[p];
        m0 = fmaxf(m0, g_ge[e * 2]);
        m1 = fmaxf(m1, g_ge[e * 2 + 1]);
    }
    #pragma unroll
    for (int o = 16; o; o >>= 1) {
        m0 = fmaxf(m0, __shfl_xor_sync(0xffffffffu, m0, o));
        m1 = fmaxf(m1, __shfl_xor_sync(0xffffffffu, m1, o));
    }
    float d0 = 0.f, d1 = 0.f;
    for (int p = s0 + lane; p < s1; p += 32) {
        int e = g_eids[p];
        d0 += expf(g_ge[e * 2] - m0);
        d1 += expf(g_ge[e * 2 + 1] - m1);
    }
    #pragma unroll
    for (int o = 16; o; o >>= 1) {
        d0 += __shfl_xor_sync(0xffffffffu, d0, o);
        d1 += __shfl_xor_sync(0xffffffffu, d1, o);
    }
    float i0 = 1.f / d0, i1 = 1.f / d1;
    for (int p = s0 + lane; p < s1; p += 32) {
        int e = g_eids[p];
        g_ge[e * 2]     = expf(g_ge[e * 2] - m0) * i0;
        g_ge[e * 2 + 1] = expf(g_ge[e * 2 + 1] - m1) * i1;
    }
}

// ---------------- GAT accumulation + bias + relu ----------------
__global__ void gat_accum(const int* __restrict__ src, const float* __restrict__ gbias) {
    int w = (blockIdx.x * blockDim.x + threadIdx.x) >> 5;
    if (w >= NN) return;
    int lane = threadIdx.x & 31;
    int s0 = g_indptr[w], s1 = g_indptr[w + 1];
    float4 a0 = make_float4(0.f, 0.f, 0.f, 0.f);
    float4 a1 = make_float4(0.f, 0.f, 0.f, 0.f);
    for (int p = s0; p < s1; p++) {
        int e = g_eids[p];
        int s = src[e];
        float al0 = g_ge[e * 2], al1 = g_ge[e * 2 + 1];
        const uint2* z2 = (const uint2*)(g_zft_h + (size_t)s * 256);
        float4 z0 = h4tof4(z2[lane]), z1 = h4tof4(z2[32 + lane]);
        a0.x += al0 * z0.x; a0.y += al0 * z0.y; a0.z += al0 * z0.z; a0.w += al0 * z0.w;
        a1.x += al1 * z1.x; a1.y += al1 * z1.y; a1.z += al1 * z1.z; a1.w += al1 * z1.w;
    }
    const float4* b4 = (const float4*)gbias;
    float4 b0 = b4[lane], b1 = b4[32 + lane];
    float4 o0, o1;
    o0.x = fmaxf(a0.x + b0.x, 0.f); o0.y = fmaxf(a0.y + b0.y, 0.f);
    o0.z = fmaxf(a0.z + b0.z, 0.f); o0.w = fmaxf(a0.w + b0.w, 0.f);
    o1.x = fmaxf(a1.x + b1.x, 0.f); o1.y = fmaxf(a1.y + b1.y, 0.f);
    o1.z = fmaxf(a1.z + b1.z, 0.f); o1.w = fmaxf(a1.w + b1.w, 0.f);
    float4* outp = (float4*)(g_rst + (size_t)w * 256);
    outp[lane] = o0;
    outp[32 + lane] = o1;
}

// ---------------- graph bounds ----------------
__global__ void graph_bounds(const int* __restrict__ gid) {
    int b = threadIdx.x;
    if (b > NG) return;
    if (b == NG) { g_gs[NG] = NN; return; }
    int lo = 0, hi = NN;
    while (lo < hi) {
        int mid = (lo + hi) >> 1;
        if (gid[mid] < b) lo = mid + 1; else hi = mid;
    }
    g_gs[b] = lo;
}

// ---------------- mean pool + classify ----------------
__global__ void pool_classify(const float* __restrict__ Wc, const float* __restrict__ bc, int gidx) {
    __shared__ float sh[256];
    int b = blockIdx.x;
    int t = threadIdx.x;
    int s = g_gs[b], e2 = g_gs[b + 1];
    float sum = 0.f;
    for (int r = s; r < e2; r++) sum += g_rst[(size_t)r * 256 + t];
    sh[t] = sum / fmaxf((float)(e2 - s), 1.f);
    __syncthreads();
    if (t < 64) {
        int hd = t >> 5, c = t & 31;
        float acc = bc[c];
        const float* hp = sh + hd * 128;
        const float* wp = Wc + c * 128;
        #pragma unroll 8
        for (int d2 = 0; d2 < 128; d2++) acc += hp[d2] * wp[d2];
        g_logits[gidx][(b * 2 + hd) * 32 + c] = acc;
    }
}

// ---------------- final distance + head softmax ----------------
__global__ void final_kernel(float* __restrict__ out) {
    int b = threadIdx.x;
    if (b >= NG) return;
    float dv[2];
    #pragma unroll
    for (int hd = 0; hd < 2; hd++) {
        float ss = 0.f;
        #pragma unroll
        for (int c = 0; c < 32; c++) {
            float df = g_logits[0][(b * 2 + hd) * 32 + c]
                     - g_logits[1][(b * 2 + hd) * 32 + c] + 1e-6f;
            ss += df * df;
        }
        dv[hd] = sqrtf(ss);
    }
    float mx = fmaxf(dv[0], dv[1]);
    float e0 = expf(dv[0] - mx), e1 = expf(dv[1] - mx);
    float inv = 1.f / (e0 + e1);
    out[b * 2] = e0 * inv;
    out[b * 2 + 1] = e1 * inv;
}

// ---------------- host driver ----------------
extern "C" void kernel_launch(void* const* d_in, const int* in_sizes, int n_in,
                              void* d_out, int out_size) {
    const float* in1  = (const float*)d_in[0];
    const float* in2  = (const float*)d_in[1];
    const int* src1 = (const int*)d_in[2];
    const int* dst1 = (const int*)d_in[3];
    const int* et1  = (const int*)d_in[4];
    const int* gid1 = (const int*)d_in[5];
    const int* src2 = (const int*)d_in[6];
    const int* dst2 = (const int*)d_in[7];
    const int* et2  = (const int*)d_in[8];
    const int* gid2 = (const int*)d_in[9];
    const float* W_et  = (const float*)d_in[10];
    const float* b_et  = (const float*)d_in[11];
    const float* W_ih  = (const float*)d_in[12];
    const float* W_hh  = (const float*)d_in[13];
    const float* b_ih  = (const float*)d_in[14];
    const float* b_hh  = (const float*)d_in[15];
    const float* W_fc  = (const float*)d_in[16];
    const float* al    = (const float*)d_in[17];
    const float* ar    = (const float*)d_in[18];
    const float* gb    = (const float*)d_in[19];
    const float* W_cls = (const float*)d_in[20];
    const float* b_cls = (const float*)d_in[21];

    const int SMEM = 2 * TILE_H2 * 4;  // A + B tiles of 128x68 half2
    static int attr_done = 0;
    if (!attr_done) {
        cudaFuncSetAttribute(gemm_all, cudaFuncAttributeMaxDynamicSharedMemorySize, SMEM);
        attr_done = 1;
    }

    // weight conversion (once per launch)
    {
        __half* p0; cudaGetSymbolAddress((void**)&p0, g_Wet_h);
        __half* p1; cudaGetSymbolAddress((void**)&p1, g_Whh_h);
        __half* p2; cudaGetSymbolAddress((void**)&p2, g_Wih_h);
        __half* p3; cudaGetSymbolAddress((void**)&p3, g_Wfc_h);
        conv_w<<<(NET * DD * DD / 2 + 255) / 256, 256>>>(W_et, p0, NET * DD * DD);
        conv_w<<<(3 * DD * DD / 2 + 255) / 256, 256>>>(W_hh, p1, 3 * DD * DD);
        conv_w<<<(3 * DD * DD / 2 + 255) / 256, 256>>>(W_ih, p2, 3 * DD * DD);
        conv_w<<<(NHEADS * DD * DD / 2 + 255) / 256, 256>>>(W_fc, p3, NHEADS * DD * DD);
    }

    const int NBLK_E = (NE + 255) / 256;
    const int NBLK_N = (NN + 255) / 256;
    const int NBLK_W = NN / 8;
    const dim3 gFused(391, 7), gGI(391, 3), gZ(391, 2);

    for (int g = 0; g < 2; g++) {
        const float* feat = g ? in2 : in1;
        const int* src = g ? src2 : src1;
        const int* dst = g ? dst2 : dst1;
        const int* et  = g ? et2 : et1;
        const int* gid = g ? gid2 : gid1;

        copy_h<<<(NN * 32 + 255) / 256, 256>>>(feat);
        zero_deg<<<NBLK_N, 256>>>();
        count_deg<<<NBLK_E, 256>>>(dst);
        scan1<<<49, 1024>>>();
        scan2<<<1, 1>>>();
        scan3<<<49, 1024>>>();
        build_eids<<<NBLK_E, 256>>>(dst);

        for (int s = 0; s < NSTEPS; s++) {
            gemm_all<<<gFused, 256, SMEM>>>(0, b_et, b_hh);
            aggregate<<<NBLK_W, 256>>>(src, et);
            gemm_all<<<gGI, 256, SMEM>>>(1, b_ih, nullptr);
            gru_update<<<(NN * 32 + 255) / 256, 256>>>();
        }
        norm_sigmoid<<<NBLK_W, 256>>>();
        gemm_all<<<gZ, 256, SMEM>>>(2, nullptr, nullptr);
        elr_kernel<<<NBLK_W, 256>>>(al, ar);
        edge_e<<<NBLK_E, 256>>>(src, dst);
        node_softmax<<<NBLK_W, 256>>>();
        gat_accum<<<NBLK_W, 256>>>(src, gb);
        graph_bounds<<<1, NG + 1>>>(gid);
        pool_classify<<<NG, 256>>>(W_cls, b_cls, g);
    }
    final_kernel<<<1, NG>>>((float*)d_out);
}